// round 2
// baseline (speedup 1.0000x reference)
#include <cuda_runtime.h>
#include <cuda_fp16.h>
#include <cstdint>

// Problem sizes (fixed by setup_inputs)
#define NN 8192   // nodes
#define DD 128    // embedding dim
#define EE 4096   // hyperedges
#define KK 8192   // reduction dim of all GEMMs
#define LN_EPS 1e-5f

// ---------------- GEMM config (Ampere-style mma.sync, baseline PTX only) -----
#define KTILE 64                       // halfs per k-chunk = 128 B rows (SW128)
#define NTILE 64
#define STAGES 4
#define NIT (KK / KTILE)               // 128 k-iterations
#define A_STAGE_BYTES (128 * 128)      // 16 KB
#define B_STAGE_BYTES (64 * 128)       // 8 KB
#define STAGE_BYTES (A_STAGE_BYTES + B_STAGE_BYTES)
#define GEMM_SMEM (STAGES * STAGE_BYTES)  // 96 KB

// ---------------- scratch (device globals; no allocation allowed) ------------
__device__ __half g_Th [(size_t)NN * NN];   // T   fp16           128 MB
__device__ __half g_TtH[(size_t)NN * NN];   // T^T fp16           128 MB
__device__ __half g_hTh[(size_t)EE * NN];   // h^T fp16            64 MB
__device__ __half g_Xh [(size_t)DD * NN];   // x^T fp16             2 MB
__device__ __half g_Tbh[(size_t)DD * NN];   // t^T fp16             2 MB
__device__ float  g_Y  [(size_t)DD * NN];   // pre-LN x^T fp32      4 MB
__device__ float  g_S  [(size_t)DD * EE];   // sums^T fp32          2 MB
__device__ float  g_counts[EE];

// ---------------- helpers ----------------
__device__ __forceinline__ uint32_t smem_u32(const void* p) {
  uint32_t a;
  asm("{ .reg .u64 t; cvta.to.shared.u64 t, %1; cvt.u32.u64 %0, t; }" : "=r"(a) : "l"(p));
  return a;
}
__device__ __forceinline__ uint32_t swz(uint32_t b) { return b ^ ((b >> 3) & 0x70); }
__device__ __forceinline__ void cp_async16(uint32_t dst, const void* src) {
  asm volatile("cp.async.cg.shared.global [%0], [%1], 16;" :: "r"(dst), "l"(src));
}
__device__ __forceinline__ void ldmatrix_x4(uint32_t& r0, uint32_t& r1, uint32_t& r2,
                                            uint32_t& r3, uint32_t addr) {
  asm volatile("ldmatrix.sync.aligned.m8n8.x4.shared.b16 {%0,%1,%2,%3}, [%4];"
               : "=r"(r0), "=r"(r1), "=r"(r2), "=r"(r3) : "r"(addr));
}
__device__ __forceinline__ void mma16816(float* c, uint32_t a0, uint32_t a1, uint32_t a2,
                                         uint32_t a3, uint32_t b0, uint32_t b1) {
  asm volatile(
      "mma.sync.aligned.m16n8k16.row.col.f32.f16.f16.f32 "
      "{%0,%1,%2,%3}, {%4,%5,%6,%7}, {%8,%9}, {%0,%1,%2,%3};"
      : "+f"(c[0]), "+f"(c[1]), "+f"(c[2]), "+f"(c[3])
      : "r"(a0), "r"(a1), "r"(a2), "r"(a3), "r"(b0), "r"(b1));
}

// ---------------- the one GEMM: C[128, Ntot] = A[128,8192] @ B[Ntot,8192]^T --
// BOUT: 0 -> fp32 C, 1 -> fp16 C
template <int BOUT>
__global__ __launch_bounds__(256, 1)
void gemm_f16(const __half* __restrict__ A, const __half* __restrict__ B,
              void* __restrict__ Cout, int ldC) {
  extern __shared__ char smem[];
  uint32_t sb = smem_u32(smem);
  const int tid = threadIdx.x;
  const int wid = tid >> 5, lane = tid & 31;
  const int n0 = blockIdx.x * NTILE;
  const int wm = (wid & 3) * 32;   // warp M offset within 128
  const int wn = (wid >> 2) * 32;  // warp N offset within 64

  // ---- per-thread cp.async mapping (6 x 16B chunks per thread per stage) ----
  // idx < 1024: A tile (128 rows x 8 chunks); idx >= 1024: B tile (64 rows)
  // ---- per-thread ldmatrix address components ----
  // A (x4): j = lane>>3 ; row = wm + mt*16 + (j&1)*8 + (lane&7) ; choff = j>>2? no: j>>1
  const int lj = lane >> 3, lr = lane & 7;
  int aRow[2], bRow[2];
  aRow[0] = wm + ((lj & 1) << 3) + lr;
  aRow[1] = aRow[0] + 16;
  const int aChO = lj >> 1;
  bRow[0] = wn + ((lj >> 1) << 3) + lr;
  bRow[1] = bRow[0] + 16;
  const int bChO = lj & 1;

  float acc[2][4][4];
#pragma unroll
  for (int i = 0; i < 2; i++)
#pragma unroll
    for (int j = 0; j < 4; j++)
#pragma unroll
      for (int q = 0; q < 4; q++) acc[i][j][q] = 0.f;

  auto load_stage = [&](int s, int kc) {
    uint32_t base = sb + s * STAGE_BYTES;
    const __half* Ak = A + kc * KTILE;
    const __half* Bk = B + (size_t)n0 * KK + kc * KTILE;
#pragma unroll
    for (int j = 0; j < 6; j++) {
      int idx = tid + j * 256;
      int c = idx & 7;
      if (idx < 1024) {
        int row = idx >> 3;
        cp_async16(base + swz(row * 128 + c * 16), Ak + (size_t)row * KK + c * 8);
      } else {
        int row = (idx - 1024) >> 3;
        cp_async16(base + A_STAGE_BYTES + swz(row * 128 + c * 16),
                   Bk + (size_t)row * KK + c * 8);
      }
    }
  };

  auto compute_stage = [&](int s) {
    uint32_t abase = sb + s * STAGE_BYTES;
    uint32_t bbase = abase + A_STAGE_BYTES;
#pragma unroll
    for (int ks = 0; ks < 4; ks++) {
      const int kc2 = ks * 2;
      uint32_t a[2][4], b[2][4];
#pragma unroll
      for (int mt = 0; mt < 2; mt++) {
        uint32_t addr = abase + aRow[mt] * 128 + (((kc2 + aChO) ^ (aRow[mt] & 7)) << 4);
        ldmatrix_x4(a[mt][0], a[mt][1], a[mt][2], a[mt][3], addr);
      }
#pragma unroll
      for (int p = 0; p < 2; p++) {
        uint32_t addr = bbase + bRow[p] * 128 + (((kc2 + bChO) ^ (bRow[p] & 7)) << 4);
        ldmatrix_x4(b[p][0], b[p][1], b[p][2], b[p][3], addr);
      }
#pragma unroll
      for (int mt = 0; mt < 2; mt++)
#pragma unroll
        for (int nt = 0; nt < 4; nt++) {
          uint32_t b0 = b[nt >> 1][(nt & 1) ? 2 : 0];
          uint32_t b1 = b[nt >> 1][(nt & 1) ? 3 : 1];
          mma16816(acc[mt][nt], a[mt][0], a[mt][1], a[mt][2], a[mt][3], b0, b1);
        }
    }
  };

  // ---- prologue ----
#pragma unroll
  for (int s = 0; s < STAGES - 1; s++) {
    load_stage(s, s);
    asm volatile("cp.async.commit_group;" ::: "memory");
  }
  // ---- main loop ----
  for (int it = 0; it < NIT; ++it) {
    int s = it & (STAGES - 1);
    asm volatile("cp.async.wait_group %0;" :: "n"(STAGES - 2) : "memory");
    __syncthreads();
    int pf = it + STAGES - 1;
    if (pf < NIT) load_stage(pf & (STAGES - 1), pf);
    asm volatile("cp.async.commit_group;" ::: "memory");  // empty group near tail keeps count
    compute_stage(s);
  }

  // ---- epilogue: direct stores ----
  const int g = lane >> 2, tg = lane & 3;
#pragma unroll
  for (int mt = 0; mt < 2; mt++)
#pragma unroll
    for (int nt = 0; nt < 4; nt++) {
      int row0 = wm + mt * 16 + g;
      int col0 = n0 + wn + nt * 8 + tg * 2;
      if (BOUT) {
        __half* C = (__half*)Cout;
        __half2 h0 = __floats2half2_rn(acc[mt][nt][0], acc[mt][nt][1]);
        __half2 h1 = __floats2half2_rn(acc[mt][nt][2], acc[mt][nt][3]);
        *(__half2*)(C + (size_t)row0 * ldC + col0) = h0;
        *(__half2*)(C + (size_t)(row0 + 8) * ldC + col0) = h1;
      } else {
        float* C = (float*)Cout;
        *(float2*)(C + (size_t)row0 * ldC + col0) = make_float2(acc[mt][nt][0], acc[mt][nt][1]);
        *(float2*)(C + (size_t)(row0 + 8) * ldC + col0) = make_float2(acc[mt][nt][2], acc[mt][nt][3]);
      }
    }
}

// ---------------- conversion / aux kernels ----------------
__global__ void k_conv_T(const float* __restrict__ T, __half* __restrict__ Th,
                         __half* __restrict__ TtH) {
  __shared__ float t[32][33];
  int c0 = blockIdx.x << 5, r0 = blockIdx.y << 5;
  int x = threadIdx.x, y = threadIdx.y;
#pragma unroll
  for (int i = 0; i < 32; i += 8) {
    float v = T[(size_t)(r0 + y + i) * NN + c0 + x];
    Th[(size_t)(r0 + y + i) * NN + c0 + x] = __float2half(v);
    t[y + i][x] = v;
  }
  __syncthreads();
#pragma unroll
  for (int i = 0; i < 32; i += 8)
    TtH[(size_t)(c0 + y + i) * NN + r0 + x] = __float2half(t[x][y + i]);
}

__global__ void k_conv_x0(const float* __restrict__ x0, __half* __restrict__ Xh) {
  __shared__ float t[32][33];
  int d0 = blockIdx.x << 5, n0 = blockIdx.y << 5;
  int x = threadIdx.x, y = threadIdx.y;
#pragma unroll
  for (int i = 0; i < 32; i += 8)
    t[y + i][x] = x0[(size_t)(n0 + y + i) * DD + d0 + x];
  __syncthreads();
#pragma unroll
  for (int i = 0; i < 32; i += 8)
    Xh[(size_t)(d0 + y + i) * NN + n0 + x] = __float2half(t[x][y + i]);
}

__global__ void k_conv_h(const int* __restrict__ h, __half* __restrict__ hTh,
                         float* __restrict__ counts) {
  __shared__ float t[32][33];
  int e0 = blockIdx.x << 5, n0 = blockIdx.y << 5;
  int x = threadIdx.x, y = threadIdx.y;
#pragma unroll
  for (int i = 0; i < 32; i += 8)
    t[y + i][x] = (h[(size_t)(n0 + y + i) * EE + e0 + x] > 0) ? 1.0f : 0.0f;
  __syncthreads();
#pragma unroll
  for (int i = 0; i < 32; i += 8) {
    float v = t[x][y + i];
    hTh[(size_t)(e0 + y + i) * NN + n0 + x] = __float2half(v);
    float s = v;
#pragma unroll
    for (int o = 16; o > 0; o >>= 1) s += __shfl_xor_sync(0xffffffffu, s, o);
    if (x == 0) atomicAdd(&counts[e0 + y + i], s);  // integer-valued -> exact, order-independent
  }
}

__global__ void k_zero(float* __restrict__ p, int n) {
  int i = blockIdx.x * blockDim.x + threadIdx.x;
  if (i < n) p[i] = 0.0f;
}

// column-wise LayerNorm over the 128 rows of Y[128, 8192] -> Xh fp16
__global__ void k_ln(const float* __restrict__ Y, const float* __restrict__ gam,
                     const float* __restrict__ bet, __half* __restrict__ Xh) {
  __shared__ float sg[DD], sb[DD];
  if (threadIdx.x < DD) {
    sg[threadIdx.x] = gam[threadIdx.x];
    sb[threadIdx.x] = bet[threadIdx.x];
  }
  __syncthreads();
  int j = blockIdx.x * blockDim.x + threadIdx.x;
  float s = 0.f, sq = 0.f;
#pragma unroll 8
  for (int d = 0; d < DD; ++d) {
    float v = Y[(size_t)d * NN + j];
    s += v; sq += v * v;
  }
  float mean = s * (1.0f / DD);
  float var = sq * (1.0f / DD) - mean * mean;
  float r = rsqrtf(var + LN_EPS);
#pragma unroll 8
  for (int d = 0; d < DD; ++d) {
    float v = Y[(size_t)d * NN + j];
    Xh[(size_t)d * NN + j] = __float2half((v - mean) * r * sg[d] + sb[d]);
  }
}

__global__ void k_final_max(const float* __restrict__ S, const float* __restrict__ counts,
                            float* __restrict__ out) {
  int d = blockIdx.x;
  float m = -3.402823466e38f;
  for (int e = threadIdx.x; e < EE; e += blockDim.x)
    m = fmaxf(m, S[(size_t)d * EE + e] / counts[e]);
#pragma unroll
  for (int o = 16; o > 0; o >>= 1) m = fmaxf(m, __shfl_xor_sync(0xffffffffu, m, o));
  __shared__ float red[4];
  int lane = threadIdx.x & 31, w = threadIdx.x >> 5;
  if (lane == 0) red[w] = m;
  __syncthreads();
  if (threadIdx.x == 0)
    out[d] = fmaxf(fmaxf(red[0], red[1]), fmaxf(red[2], red[3]));
}

// ---------------- launch ----------------
extern "C" void kernel_launch(void* const* d_in, const int* in_sizes, int n_in,
                              void* d_out, int out_size) {
  const float* x0  = (const float*)d_in[0];  // [8192,128]
  const float* T   = (const float*)d_in[1];  // [8192,8192]
  const float* gam = (const float*)d_in[2];  // [128]
  const float* bet = (const float*)d_in[3];  // [128]
  const int*   h   = (const int*)d_in[4];    // [8192,4096]
  float* out = (float*)d_out;                // [128]

  __half *Th, *TtH, *hTh, *Xh, *Tbh;
  float *Y, *S, *counts;
  cudaGetSymbolAddress((void**)&Th,  g_Th);
  cudaGetSymbolAddress((void**)&TtH, g_TtH);
  cudaGetSymbolAddress((void**)&hTh, g_hTh);
  cudaGetSymbolAddress((void**)&Xh,  g_Xh);
  cudaGetSymbolAddress((void**)&Tbh, g_Tbh);
  cudaGetSymbolAddress((void**)&Y,   g_Y);
  cudaGetSymbolAddress((void**)&S,   g_S);
  cudaGetSymbolAddress((void**)&counts, g_counts);

  cudaFuncSetAttribute(gemm_f16<0>, cudaFuncAttributeMaxDynamicSharedMemorySize, GEMM_SMEM);
  cudaFuncSetAttribute(gemm_f16<1>, cudaFuncAttributeMaxDynamicSharedMemorySize, GEMM_SMEM);

  dim3 b328(32, 8);
  k_conv_T <<<dim3(NN / 32, NN / 32), b328>>>(T, Th, TtH);
  k_conv_x0<<<dim3(DD / 32, NN / 32), b328>>>(x0, Xh);
  k_zero<<<(EE + 255) / 256, 256>>>(counts, EE);
  k_conv_h <<<dim3(EE / 32, NN / 32), b328>>>(h, hTh, counts);

  for (int l = 0; l < 3; ++l) {  // num_layers fixed at 3 by setup_inputs
    gemm_f16<1><<<NN / NTILE, 256, GEMM_SMEM>>>(Xh, Th, Tbh, NN);   // t^T  (fp16 out)
    gemm_f16<0><<<NN / NTILE, 256, GEMM_SMEM>>>(Tbh, TtH, Y, NN);   // pre-LN x^T (fp32)
    k_ln<<<NN / 256, 256>>>(Y, gam, bet, Xh);
  }
  gemm_f16<0><<<EE / NTILE, 256, GEMM_SMEM>>>(Xh, hTh, S, EE);      // sums^T
  k_final_max<<<DD, 128>>>(S, counts, out);
}

// round 4
// speedup vs baseline: 1.2033x; 1.2033x over previous
#include <cuda_runtime.h>
#include <cuda_fp16.h>
#include <cstdint>

// Problem sizes (fixed by setup_inputs)
#define NN 8192   // nodes
#define DD 128    // embedding dim
#define EE 4096   // hyperedges
#define KK 8192   // reduction dim of the big GEMMs
#define LN_EPS 1e-5f

// ---------------- GEMM config (Ampere-style mma.sync, baseline PTX only) -----
#define KTILE 64                       // halfs per k-chunk = 128 B rows (SW128)
#define NTILE 64
#define STAGES 4
#define NIT (KK / KTILE)               // 128 k-iterations (full K)
#define A_STAGE_BYTES (128 * 128)      // 16 KB
#define B_STAGE_BYTES (64 * 128)       // 8 KB
#define STAGE_BYTES (A_STAGE_BYTES + B_STAGE_BYTES)
#define GEMM_SMEM (STAGES * STAGE_BYTES)  // 96 KB

// ---------------- scratch (device globals; no allocation allowed) ------------
__device__ __half g_Th [(size_t)NN * NN];   // T fp16             128 MB
__device__ __half g_hH [(size_t)NN * EE];   // h fp16 [N,E]        64 MB
__device__ __half g_Xh [(size_t)DD * NN];   // x^T fp16             2 MB
__device__ __half g_Tbh[(size_t)DD * NN];   // t^T fp16             2 MB
__device__ float  g_S  [(size_t)2 * DD * EE];  // sums^T partials    4 MB
__device__ float  g_counts[EE];

// ---------------- helpers ----------------
__device__ __forceinline__ uint32_t h2u(__half2 h) {
  uint32_t u;
  *reinterpret_cast<__half2*>(&u) = h;
  return u;
}
__device__ __forceinline__ uint32_t smem_u32(const void* p) {
  uint32_t a;
  asm("{ .reg .u64 t; cvta.to.shared.u64 t, %1; cvt.u32.u64 %0, t; }" : "=r"(a) : "l"(p));
  return a;
}
__device__ __forceinline__ uint32_t swz(uint32_t b) { return b ^ ((b >> 3) & 0x70); }
__device__ __forceinline__ void cp_async16(uint32_t dst, const void* src) {
  asm volatile("cp.async.cg.shared.global [%0], [%1], 16;" :: "r"(dst), "l"(src));
}
__device__ __forceinline__ void ldmatrix_x4(uint32_t& r0, uint32_t& r1, uint32_t& r2,
                                            uint32_t& r3, uint32_t addr) {
  asm volatile("ldmatrix.sync.aligned.m8n8.x4.shared.b16 {%0,%1,%2,%3}, [%4];"
               : "=r"(r0), "=r"(r1), "=r"(r2), "=r"(r3) : "r"(addr));
}
__device__ __forceinline__ void ldmatrix_x4t(uint32_t& r0, uint32_t& r1, uint32_t& r2,
                                             uint32_t& r3, uint32_t addr) {
  asm volatile("ldmatrix.sync.aligned.m8n8.x4.trans.shared.b16 {%0,%1,%2,%3}, [%4];"
               : "=r"(r0), "=r"(r1), "=r"(r2), "=r"(r3) : "r"(addr));
}
__device__ __forceinline__ void mma16816(float* c, uint32_t a0, uint32_t a1, uint32_t a2,
                                         uint32_t a3, uint32_t b0, uint32_t b1) {
  asm volatile(
      "mma.sync.aligned.m16n8k16.row.col.f32.f16.f16.f32 "
      "{%0,%1,%2,%3}, {%4,%5,%6,%7}, {%8,%9}, {%0,%1,%2,%3};"
      : "+f"(c[0]), "+f"(c[1]), "+f"(c[2]), "+f"(c[3])
      : "r"(a0), "r"(a1), "r"(a2), "r"(a3), "r"(b0), "r"(b1));
}

// ============ GEMM 1: C[128,Ntot] = A[128,K] @ B[Ntot,K]^T, B K-major =========
// (B row n contiguous along k). Output fp16.
__global__ __launch_bounds__(256, 1)
void gemm_nt(const __half* __restrict__ A, const __half* __restrict__ B,
             __half* __restrict__ C, int ldC) {
  extern __shared__ char smem[];
  uint32_t sb = smem_u32(smem);
  const int tid = threadIdx.x;
  const int wid = tid >> 5, lane = tid & 31;
  const int n0 = blockIdx.x * NTILE;
  const int wm = (wid & 3) * 32;
  const int wn = (wid >> 2) * 32;

  const int lj = lane >> 3, lr = lane & 7;
  int aRow[2], bRow[2];
  aRow[0] = wm + ((lj & 1) << 3) + lr;
  aRow[1] = aRow[0] + 16;
  const int aChO = lj >> 1;
  bRow[0] = wn + ((lj >> 1) << 3) + lr;
  bRow[1] = bRow[0] + 16;
  const int bChO = lj & 1;

  float acc[2][4][4];
#pragma unroll
  for (int i = 0; i < 2; i++)
#pragma unroll
    for (int j = 0; j < 4; j++)
#pragma unroll
      for (int q = 0; q < 4; q++) acc[i][j][q] = 0.f;

  auto load_stage = [&](int s, int kc) {
    uint32_t base = sb + s * STAGE_BYTES;
    const __half* Ak = A + kc * KTILE;
    const __half* Bk = B + (size_t)n0 * KK + kc * KTILE;
#pragma unroll
    for (int j = 0; j < 6; j++) {
      int idx = tid + j * 256;
      int c = idx & 7;
      if (idx < 1024) {
        int row = idx >> 3;
        cp_async16(base + swz(row * 128 + c * 16), Ak + (size_t)row * KK + c * 8);
      } else {
        int row = (idx - 1024) >> 3;
        cp_async16(base + A_STAGE_BYTES + swz(row * 128 + c * 16),
                   Bk + (size_t)row * KK + c * 8);
      }
    }
  };

  auto compute_stage = [&](int s) {
    uint32_t abase = sb + s * STAGE_BYTES;
    uint32_t bbase = abase + A_STAGE_BYTES;
#pragma unroll
    for (int ks = 0; ks < 4; ks++) {
      const int kc2 = ks * 2;
      uint32_t a[2][4], b[2][4];
#pragma unroll
      for (int mt = 0; mt < 2; mt++) {
        uint32_t addr = abase + aRow[mt] * 128 + (((kc2 + aChO) ^ (aRow[mt] & 7)) << 4);
        ldmatrix_x4(a[mt][0], a[mt][1], a[mt][2], a[mt][3], addr);
      }
#pragma unroll
      for (int p = 0; p < 2; p++) {
        uint32_t addr = bbase + bRow[p] * 128 + (((kc2 + bChO) ^ (bRow[p] & 7)) << 4);
        ldmatrix_x4(b[p][0], b[p][1], b[p][2], b[p][3], addr);
      }
#pragma unroll
      for (int mt = 0; mt < 2; mt++)
#pragma unroll
        for (int nt = 0; nt < 4; nt++) {
          uint32_t b0 = b[nt >> 1][(nt & 1) ? 2 : 0];
          uint32_t b1 = b[nt >> 1][(nt & 1) ? 3 : 1];
          mma16816(acc[mt][nt], a[mt][0], a[mt][1], a[mt][2], a[mt][3], b0, b1);
        }
    }
  };

#pragma unroll
  for (int s = 0; s < STAGES - 1; s++) {
    load_stage(s, s);
    asm volatile("cp.async.commit_group;" ::: "memory");
  }
  for (int it = 0; it < NIT; ++it) {
    int s = it & (STAGES - 1);
    asm volatile("cp.async.wait_group %0;" :: "n"(STAGES - 2) : "memory");
    __syncthreads();
    int pf = it + STAGES - 1;
    if (pf < NIT) load_stage(pf & (STAGES - 1), pf);
    asm volatile("cp.async.commit_group;" ::: "memory");
    compute_stage(s);
  }

  const int g = lane >> 2, tg = lane & 3;
#pragma unroll
  for (int mt = 0; mt < 2; mt++)
#pragma unroll
    for (int nt = 0; nt < 4; nt++) {
      int row0 = wm + mt * 16 + g;
      int col0 = n0 + wn + nt * 8 + tg * 2;
      __half2 h0 = __floats2half2_rn(acc[mt][nt][0], acc[mt][nt][1]);
      __half2 h1 = __floats2half2_rn(acc[mt][nt][2], acc[mt][nt][3]);
      *(__half2*)(C + (size_t)row0 * ldC + col0) = h0;
      *(__half2*)(C + (size_t)(row0 + 8) * ldC + col0) = h1;
    }
}

// ===== GEMM 2: C[128,Ntot] = A[128,K] @ B[K,Ntot], B N-major (trans-ldmatrix) =
// LNF=1: fuse column LayerNorm over the 128 M-rows, write fp16.
// LNF=0: write fp32 partials (split-K capable via kIters/kOff/Cout offset).
template <int LNF>
__global__ __launch_bounds__(256, 1)
void gemm_tn(const __half* __restrict__ A, const __half* __restrict__ B, int ldB,
             int kIters, void* __restrict__ Cout, int ldC,
             const float* __restrict__ gam, const float* __restrict__ bet) {
  extern __shared__ char smem[];
  uint32_t sb = smem_u32(smem);
  const int tid = threadIdx.x;
  const int wid = tid >> 5, lane = tid & 31;
  const int n0 = blockIdx.x * NTILE;
  const int kOff = blockIdx.y * kIters;  // in KTILE units
  const int wm = (wid & 3) * 32;
  const int wn = (wid >> 2) * 32;

  const int lj = lane >> 3, lr = lane & 7;
  int aRow[2];
  aRow[0] = wm + ((lj & 1) << 3) + lr;
  aRow[1] = aRow[0] + 16;
  const int aChO = lj >> 1;
  // trans-B ldmatrix address components
  const int bKsub = ((lj & 1) << 3) + lr;    // k within 16-block
  const int bChSub = (wn >> 3) + (lj >> 1);  // chunk: wn/8 + (mi>>1), +p*2 later

  float acc[2][4][4];
#pragma unroll
  for (int i = 0; i < 2; i++)
#pragma unroll
    for (int j = 0; j < 4; j++)
#pragma unroll
      for (int q = 0; q < 4; q++) acc[i][j][q] = 0.f;

  auto load_stage = [&](int s, int kc) {
    uint32_t base = sb + s * STAGE_BYTES;
    const __half* Ak = A + (size_t)kc * KTILE;
    const __half* Bk = B + (size_t)kc * KTILE * ldB + n0;
#pragma unroll
    for (int j = 0; j < 6; j++) {
      int idx = tid + j * 256;
      int c = idx & 7;
      if (idx < 1024) {
        int row = idx >> 3;
        cp_async16(base + swz(row * 128 + c * 16), Ak + (size_t)row * KK + c * 8);
      } else {
        int row = (idx - 1024) >> 3;  // k-row within tile
        cp_async16(base + A_STAGE_BYTES + swz(row * 128 + c * 16),
                   Bk + (size_t)row * ldB + c * 8);
      }
    }
  };

  auto compute_stage = [&](int s) {
    uint32_t abase = sb + s * STAGE_BYTES;
    uint32_t bbase = abase + A_STAGE_BYTES;
#pragma unroll
    for (int ks = 0; ks < 4; ks++) {
      const int kc2 = ks * 2;
      uint32_t a[2][4], b[2][4];
#pragma unroll
      for (int mt = 0; mt < 2; mt++) {
        uint32_t addr = abase + aRow[mt] * 128 + (((kc2 + aChO) ^ (aRow[mt] & 7)) << 4);
        ldmatrix_x4(a[mt][0], a[mt][1], a[mt][2], a[mt][3], addr);
      }
#pragma unroll
      for (int p = 0; p < 2; p++) {
        int krow = ks * 16 + bKsub;
        int chunk = bChSub + p * 2;
        uint32_t addr = bbase + krow * 128 + ((chunk ^ (krow & 7)) << 4);
        ldmatrix_x4t(b[p][0], b[p][1], b[p][2], b[p][3], addr);
      }
#pragma unroll
      for (int mt = 0; mt < 2; mt++)
#pragma unroll
        for (int nt = 0; nt < 4; nt++) {
          // nt = p*2 + q : b0 = b[p][2q], b1 = b[p][2q+1]
          uint32_t b0 = b[nt >> 1][(nt & 1) << 1];
          uint32_t b1 = b[nt >> 1][((nt & 1) << 1) + 1];
          mma16816(acc[mt][nt], a[mt][0], a[mt][1], a[mt][2], a[mt][3], b0, b1);
        }
    }
  };

#pragma unroll
  for (int s = 0; s < STAGES - 1; s++) {
    load_stage(s, kOff + s);
    asm volatile("cp.async.commit_group;" ::: "memory");
  }
  for (int it = 0; it < kIters; ++it) {
    int s = it & (STAGES - 1);
    asm volatile("cp.async.wait_group %0;" :: "n"(STAGES - 2) : "memory");
    __syncthreads();
    int pf = it + STAGES - 1;
    if (pf < kIters) load_stage(pf & (STAGES - 1), kOff + pf);
    asm volatile("cp.async.commit_group;" ::: "memory");
    compute_stage(s);
  }

  const int g = lane >> 2, tg = lane & 3;

  if (LNF) {
    // drain all async copies before reusing smem for the LN reduction
    asm volatile("cp.async.wait_group 0;" ::: "memory");
    __syncthreads();
    float* s_sum = reinterpret_cast<float*>(smem);          // [4][64]
    float* s_sq  = reinterpret_cast<float*>(smem) + 256;    // [4][64]

    float ps[4][2], pq[4][2];
#pragma unroll
    for (int nt = 0; nt < 4; nt++)
#pragma unroll
      for (int j = 0; j < 2; j++) {
        float sv = 0.f, qv = 0.f;
#pragma unroll
        for (int mt = 0; mt < 2; mt++) {
          float v0 = acc[mt][nt][j], v1 = acc[mt][nt][j + 2];
          sv += v0 + v1;
          qv += v0 * v0 + v1 * v1;
        }
#pragma unroll
        for (int o = 4; o < 32; o <<= 1) {
          sv += __shfl_xor_sync(0xffffffffu, sv, o);
          qv += __shfl_xor_sync(0xffffffffu, qv, o);
        }
        ps[nt][j] = sv;
        pq[nt][j] = qv;
      }
    if (g == 0) {
      int mw = wid & 3;
#pragma unroll
      for (int nt = 0; nt < 4; nt++)
#pragma unroll
        for (int j = 0; j < 2; j++) {
          int col = wn + nt * 8 + tg * 2 + j;
          s_sum[mw * 64 + col] = ps[nt][j];
          s_sq[mw * 64 + col] = pq[nt][j];
        }
    }
    __syncthreads();

    float mean[4][2], rinv[4][2];
#pragma unroll
    for (int nt = 0; nt < 4; nt++)
#pragma unroll
      for (int j = 0; j < 2; j++) {
        int col = wn + nt * 8 + tg * 2 + j;
        float tot = s_sum[col] + s_sum[64 + col] + s_sum[128 + col] + s_sum[192 + col];
        float tq  = s_sq[col] + s_sq[64 + col] + s_sq[128 + col] + s_sq[192 + col];
        float m = tot * (1.0f / DD);
        float var = tq * (1.0f / DD) - m * m;
        mean[nt][j] = m;
        rinv[nt][j] = rsqrtf(var + LN_EPS);
      }

    __half* C = (__half*)Cout;
#pragma unroll
    for (int mt = 0; mt < 2; mt++) {
      int r0 = wm + mt * 16 + g;
      float g0 = gam[r0], b0 = bet[r0];
      float g1 = gam[r0 + 8], b1 = bet[r0 + 8];
#pragma unroll
      for (int nt = 0; nt < 4; nt++) {
        int col0 = n0 + wn + nt * 8 + tg * 2;
        float y00 = (acc[mt][nt][0] - mean[nt][0]) * rinv[nt][0] * g0 + b0;
        float y01 = (acc[mt][nt][1] - mean[nt][1]) * rinv[nt][1] * g0 + b0;
        float y10 = (acc[mt][nt][2] - mean[nt][0]) * rinv[nt][0] * g1 + b1;
        float y11 = (acc[mt][nt][3] - mean[nt][1]) * rinv[nt][1] * g1 + b1;
        *(__half2*)(C + (size_t)r0 * ldC + col0) = __floats2half2_rn(y00, y01);
        *(__half2*)(C + (size_t)(r0 + 8) * ldC + col0) = __floats2half2_rn(y10, y11);
      }
    }
  } else {
    float* C = (float*)Cout + (size_t)blockIdx.y * DD * EE;  // split-K partial slab
#pragma unroll
    for (int mt = 0; mt < 2; mt++)
#pragma unroll
      for (int nt = 0; nt < 4; nt++) {
        int row0 = wm + mt * 16 + g;
        int col0 = n0 + wn + nt * 8 + tg * 2;
        *(float2*)(C + (size_t)row0 * ldC + col0) =
            make_float2(acc[mt][nt][0], acc[mt][nt][1]);
        *(float2*)(C + (size_t)(row0 + 8) * ldC + col0) =
            make_float2(acc[mt][nt][2], acc[mt][nt][3]);
      }
  }
}

// ---------------- conversion / aux kernels ----------------
// streaming fp32 -> fp16 (T)
__global__ void k_convT(const float* __restrict__ T, __half* __restrict__ Th) {
  size_t i = (size_t)blockIdx.x * blockDim.x + threadIdx.x;
  size_t n8 = (size_t)NN * NN / 8;
  const float4* src = (const float4*)T;
  uint4* dst = (uint4*)Th;
  for (size_t j = i; j < n8; j += (size_t)gridDim.x * blockDim.x) {
    float4 a = src[2 * j], b = src[2 * j + 1];
    uint4 o;
    o.x = h2u(__floats2half2_rn(a.x, a.y));
    o.y = h2u(__floats2half2_rn(a.z, a.w));
    o.z = h2u(__floats2half2_rn(b.x, b.y));
    o.w = h2u(__floats2half2_rn(b.z, b.w));
    dst[j] = o;
  }
}

// x0 [N,128] fp32 -> Xh [128,N] fp16 (transpose)
__global__ void k_conv_x0(const float* __restrict__ x0, __half* __restrict__ Xh) {
  __shared__ float t[32][33];
  int d0 = blockIdx.x << 5, n0 = blockIdx.y << 5;
  int x = threadIdx.x, y = threadIdx.y;
#pragma unroll
  for (int i = 0; i < 32; i += 8)
    t[y + i][x] = x0[(size_t)(n0 + y + i) * DD + d0 + x];
  __syncthreads();
#pragma unroll
  for (int i = 0; i < 32; i += 8)
    Xh[(size_t)(d0 + y + i) * NN + n0 + x] = __float2half(t[x][y + i]);
}

// h [N,E] int32 -> hH [N,E] fp16 (streaming) + counts (exact, order-indep)
__global__ void k_conv_h(const int* __restrict__ h, __half* __restrict__ hH,
                         float* __restrict__ counts) {
  int e0 = blockIdx.x * 1024 + threadIdx.x * 4;
  int n0 = blockIdx.y * 64;
  float cnt0 = 0.f, cnt1 = 0.f, cnt2 = 0.f, cnt3 = 0.f;
#pragma unroll 2
  for (int r = 0; r < 64; r++) {
    int4 v = *(const int4*)(h + (size_t)(n0 + r) * EE + e0);
    float f0 = (v.x > 0) ? 1.f : 0.f, f1 = (v.y > 0) ? 1.f : 0.f;
    float f2 = (v.z > 0) ? 1.f : 0.f, f3 = (v.w > 0) ? 1.f : 0.f;
    uint2 o;
    o.x = h2u(__floats2half2_rn(f0, f1));
    o.y = h2u(__floats2half2_rn(f2, f3));
    *(uint2*)(hH + (size_t)(n0 + r) * EE + e0) = o;
    cnt0 += f0; cnt1 += f1; cnt2 += f2; cnt3 += f3;
  }
  atomicAdd(&counts[e0], cnt0);
  atomicAdd(&counts[e0 + 1], cnt1);
  atomicAdd(&counts[e0 + 2], cnt2);
  atomicAdd(&counts[e0 + 3], cnt3);
}

__global__ void k_zero(float* __restrict__ p, int n) {
  int i = blockIdx.x * blockDim.x + threadIdx.x;
  if (i < n) p[i] = 0.0f;
}

// max over e of (S0+S1)/counts per d
__global__ void k_final_max(const float* __restrict__ S, const float* __restrict__ counts,
                            float* __restrict__ out) {
  int d = blockIdx.x;
  const float* S0 = S + (size_t)d * EE;
  const float* S1 = S + (size_t)DD * EE + (size_t)d * EE;
  float m = -3.402823466e38f;
  for (int e = threadIdx.x; e < EE; e += blockDim.x)
    m = fmaxf(m, (S0[e] + S1[e]) / counts[e]);
#pragma unroll
  for (int o = 16; o > 0; o >>= 1) m = fmaxf(m, __shfl_xor_sync(0xffffffffu, m, o));
  __shared__ float red[4];
  int lane = threadIdx.x & 31, w = threadIdx.x >> 5;
  if (lane == 0) red[w] = m;
  __syncthreads();
  if (threadIdx.x == 0)
    out[d] = fmaxf(fmaxf(red[0], red[1]), fmaxf(red[2], red[3]));
}

// ---------------- launch ----------------
extern "C" void kernel_launch(void* const* d_in, const int* in_sizes, int n_in,
                              void* d_out, int out_size) {
  const float* x0  = (const float*)d_in[0];  // [8192,128]
  const float* T   = (const float*)d_in[1];  // [8192,8192]
  const float* gam = (const float*)d_in[2];  // [128]
  const float* bet = (const float*)d_in[3];  // [128]
  const int*   h   = (const int*)d_in[4];    // [8192,4096]
  float* out = (float*)d_out;                // [128]

  __half *Th, *hH, *Xh, *Tbh;
  float *S, *counts;
  cudaGetSymbolAddress((void**)&Th,  g_Th);
  cudaGetSymbolAddress((void**)&hH,  g_hH);
  cudaGetSymbolAddress((void**)&Xh,  g_Xh);
  cudaGetSymbolAddress((void**)&Tbh, g_Tbh);
  cudaGetSymbolAddress((void**)&S,   g_S);
  cudaGetSymbolAddress((void**)&counts, g_counts);

  cudaFuncSetAttribute(gemm_nt, cudaFuncAttributeMaxDynamicSharedMemorySize, GEMM_SMEM);
  cudaFuncSetAttribute(gemm_tn<0>, cudaFuncAttributeMaxDynamicSharedMemorySize, GEMM_SMEM);
  cudaFuncSetAttribute(gemm_tn<1>, cudaFuncAttributeMaxDynamicSharedMemorySize, GEMM_SMEM);

  k_convT<<<4096, 256>>>(T, Th);
  k_conv_x0<<<dim3(DD / 32, NN / 32), dim3(32, 8)>>>(x0, Xh);
  k_zero<<<(EE + 255) / 256, 256>>>(counts, EE);
  k_conv_h<<<dim3(EE / 1024, NN / 64), 256>>>(h, hH, counts);

  for (int l = 0; l < 3; ++l) {  // num_layers fixed at 3 by setup_inputs
    // t^T = (T x)^T : B = T, K-major rows
    gemm_nt<<<NN / NTILE, 256, GEMM_SMEM>>>(Xh, Th, Tbh, NN);
    // x^T = (T^T t)^T : B = T accessed [k][n] (trans), LN fused
    gemm_tn<1><<<dim3(NN / NTILE, 1), 256, GEMM_SMEM>>>(
        Tbh, Th, NN, NIT, Xh, NN, gam, bet);
  }
  // sums^T = x^T @ h : B = hH accessed [n][e] (trans), split-K=2
  gemm_tn<0><<<dim3(EE / NTILE, 2), 256, GEMM_SMEM>>>(
      Xh, hH, EE, NIT / 2, S, EE, gam, bet);
  k_final_max<<<DD, 128>>>(S, counts, out);
}